// round 5
// baseline (speedup 1.0000x reference)
#include <cuda_runtime.h>

// ---------------------------------------------------------------------------
// Transformer-XL relative attention, fp32 baseline.
//
// Shapes: BSZ=4, QLEN=1024, KLEN=2048, N_HEAD=16, D_HEAD=64, D_MODEL=1024
// MEM_LEN = 1024. Mask: query i attends to j <= i + 1024.
// rel_shift(BD)[b,i,j] == BD[b,i, j - i + 1023] for all unmasked (i,j).
// ---------------------------------------------------------------------------

#define BSZ 4
#define QLEN 1024
#define KLEN 2048
#define NHEAD 16
#define DHEAD 64
#define DMODEL 1024

// Scratch (allocation-free rule: __device__ globals)
__device__ float g_q [BSZ * QLEN * DMODEL];          // 16 MB  q = w_tail @ Wq
__device__ float g_kv[BSZ * KLEN * 2 * DMODEL];      // 64 MB  kv = w @ Wkv
__device__ float g_rk[KLEN * DMODEL];                //  8 MB  rk = r @ Wr
__device__ float g_av[BSZ * QLEN * DMODEL];          // 16 MB  attn_vec

// ---------------------------------------------------------------------------
// Tiled SGEMM: C[M,N] = A[M,K] @ B[K,N].  64x64 tile, BK=16, 256 thr, 4x4 micro.
// GATHER=1: A row m maps to w row (m/1024)*2048 + 1024 + (m%1024)  (q proj).
// ---------------------------------------------------------------------------
template<int GATHER>
__global__ void sgemm_kernel(const float* __restrict__ A,
                             const float* __restrict__ B,
                             float* __restrict__ C,
                             int M, int N, int K)
{
    __shared__ float As[16][64];
    __shared__ float Bs[16][68];   // +4 pad to dodge conflicts

    const int tid = threadIdx.x;           // 0..255
    const int tx = tid & 15;               // 0..15
    const int ty = tid >> 4;               // 0..15
    const int bm = blockIdx.y * 64;
    const int bn = blockIdx.x * 64;

    float acc[4][4] = {};

    for (int k0 = 0; k0 < K; k0 += 16) {
        // A tile: 64 rows x 16 k
        #pragma unroll
        for (int i = 0; i < 4; i++) {
            int idx = tid + i * 256;       // 0..1023
            int m  = idx >> 4;
            int kk = idx & 15;
            int gm = bm + m;
            long row = GATHER ? ((long)(gm >> 10) * KLEN + QLEN + (gm & 1023))
                              : (long)gm;
            As[kk][m] = A[row * K + k0 + kk];
        }
        // B tile: 16 k x 64 n
        #pragma unroll
        for (int i = 0; i < 4; i++) {
            int idx = tid + i * 256;
            int kk = idx >> 6;
            int nn = idx & 63;
            Bs[kk][nn] = B[(long)(k0 + kk) * N + bn + nn];
        }
        __syncthreads();

        #pragma unroll
        for (int kk = 0; kk < 16; kk++) {
            float a[4], b[4];
            #pragma unroll
            for (int i = 0; i < 4; i++) a[i] = As[kk][ty * 4 + i];
            #pragma unroll
            for (int j = 0; j < 4; j++) b[j] = Bs[kk][tx * 4 + j];
            #pragma unroll
            for (int i = 0; i < 4; i++)
                #pragma unroll
                for (int j = 0; j < 4; j++)
                    acc[i][j] += a[i] * b[j];
        }
        __syncthreads();
    }

    #pragma unroll
    for (int i = 0; i < 4; i++)
        #pragma unroll
        for (int j = 0; j < 4; j++)
            C[(long)(bm + ty * 4 + i) * N + bn + tx * 4 + j] = acc[i][j];
}

// ---------------------------------------------------------------------------
// Fused relative attention. grid = (QLEN, NHEAD, BSZ), block = 128 threads.
// One block handles one (b, n, i) query row:
//   s_j = [ (q+rwb)·k_j + (q+rrb)·rk_{j-i+1023} ] * 1/8   for j in [0, i+1024]
//   softmax over j, then out_d = sum_j p_j * v[j, d]
// ---------------------------------------------------------------------------
__global__ void attn_kernel(const float* __restrict__ rwb,
                            const float* __restrict__ rrb)
{
    __shared__ float s[KLEN];
    __shared__ float qw[DHEAD];
    __shared__ float qr[DHEAD];
    __shared__ float red[128];

    const int i = blockIdx.x;
    const int n = blockIdx.y;
    const int b = blockIdx.z;
    const int tid = threadIdx.x;           // 0..127
    const int count = i + 1025;            // j in [0, i+1024]

    const float* qrow = g_q + (long)(b * QLEN + i) * DMODEL + n * DHEAD;
    if (tid < 64) {
        qw[tid] = qrow[tid] + rwb[n * DHEAD + tid];
    } else {
        int d = tid - 64;
        qr[d] = qrow[d] + rrb[n * DHEAD + d];
    }
    __syncthreads();

    const float scale = 0.125f;            // 1/sqrt(64)

    // --- scores ---
    for (int j = tid; j < count; j += 128) {
        const float* krow  = g_kv + (long)(b * KLEN + j) * (2 * DMODEL) + n * DHEAD;
        const float* rkrow = g_rk + (long)(j - i + 1023) * DMODEL + n * DHEAD;
        float acc = 0.f;
        #pragma unroll
        for (int d = 0; d < DHEAD; d++)
            acc += qw[d] * krow[d] + qr[d] * rkrow[d];
        s[j] = acc * scale;
    }
    __syncthreads();

    // --- max reduce ---
    float m = -1e30f;
    for (int j = tid; j < count; j += 128) m = fmaxf(m, s[j]);
    red[tid] = m;
    __syncthreads();
    #pragma unroll
    for (int o = 64; o > 0; o >>= 1) {
        if (tid < o) red[tid] = fmaxf(red[tid], red[tid + o]);
        __syncthreads();
    }
    m = red[0];
    __syncthreads();

    // --- exp + sum reduce ---
    float sum = 0.f;
    for (int j = tid; j < count; j += 128) {
        float e = __expf(s[j] - m);
        s[j] = e;
        sum += e;
    }
    red[tid] = sum;
    __syncthreads();
    #pragma unroll
    for (int o = 64; o > 0; o >>= 1) {
        if (tid < o) red[tid] += red[tid + o];
        __syncthreads();
    }
    const float inv = 1.f / red[0];
    __syncthreads();

    // --- prob @ V : thread t handles d = t&63, j-group = t>>6 ---
    const int d = tid & 63;
    const int grp = tid >> 6;
    float acc = 0.f;
    const float* vbase = g_kv + (long)b * KLEN * (2 * DMODEL) + DMODEL + n * DHEAD + d;
    for (int j = grp; j < count; j += 2)
        acc += s[j] * vbase[(long)j * (2 * DMODEL)];
    red[tid] = acc;
    __syncthreads();
    if (tid < 64)
        g_av[(long)(b * QLEN + i) * DMODEL + n * DHEAD + d] =
            (red[tid] + red[tid + 64]) * inv;
}

// ---------------------------------------------------------------------------
extern "C" void kernel_launch(void* const* d_in, const int* in_sizes, int n_in,
                              void* d_out, int out_size)
{
    const float* w   = (const float*)d_in[0];  // [4,2048,1024]
    const float* r   = (const float*)d_in[1];  // [1,2048,1024]
    const float* rwb = (const float*)d_in[2];  // [16,64]
    const float* rrb = (const float*)d_in[3];  // [16,64]
    const float* Wq  = (const float*)d_in[4];  // [1024,1024]
    const float* Wkv = (const float*)d_in[5];  // [1024,2048]
    const float* Wr  = (const float*)d_in[6];  // [1024,1024]
    const float* Wo  = (const float*)d_in[7];  // [1024,1024]
    // d_in[8] = attn_mask (recomputed analytically), d_in[9] = qlen (static)
    float* out = (float*)d_out;

    float *q, *kv, *rk, *av;
    cudaGetSymbolAddress((void**)&q,  g_q);
    cudaGetSymbolAddress((void**)&kv, g_kv);
    cudaGetSymbolAddress((void**)&rk, g_rk);
    cudaGetSymbolAddress((void**)&av, g_av);

    const dim3 thr(256);

    // q = w[:, -1024:, :] @ Wq         -> [4096, 1024]
    sgemm_kernel<1><<<dim3(1024 / 64, 4096 / 64), thr>>>(w, Wq, q, 4096, 1024, 1024);
    // kv = w @ Wkv                     -> [8192, 2048]
    sgemm_kernel<0><<<dim3(2048 / 64, 8192 / 64), thr>>>(w, Wkv, kv, 8192, 2048, 1024);
    // rk = r @ Wr                      -> [2048, 1024]
    sgemm_kernel<0><<<dim3(1024 / 64, 2048 / 64), thr>>>(r, Wr, rk, 2048, 1024, 1024);
    // fused relative attention         -> g_av [4096, 1024]
    attn_kernel<<<dim3(QLEN, NHEAD, BSZ), 128>>>(rwb, rrb);
    // out = attn_vec @ Wo              -> [4096, 1024]
    sgemm_kernel<0><<<dim3(1024 / 64, 4096 / 64), thr>>>(av, Wo, out, 4096, 1024, 1024);
}